// round 3
// baseline (speedup 1.0000x reference)
#include <cuda_runtime.h>
#include <math.h>

// Problem constants
#define B_   8
#define S_   1024
#define D_   512
#define NH_  8
#define HD_  64
#define MT_  (B_ * S_)      // 8192 rows
#define BH_  (B_ * NH_)     // 64 batch*head

// -------- device scratch (allocation-free: static __device__ globals) --------
__device__ float g_qh[MT_ * D_];
__device__ float g_kh[MT_ * D_];
__device__ float g_vh[MT_ * D_];
__device__ float g_ph[MT_ * D_];
__device__ float g_ctx[MT_ * D_];
__device__ int   g_mask_mode;                    // 0=u8, 1=i32, 2=f32

// ---------------------------------------------------------------------------
// Mask dtype detector (bool not in harness dtype list; sniff deterministically)
// ---------------------------------------------------------------------------
__global__ void detect_mask_kernel(const void* __restrict__ mask) {
    if (threadIdx.x != 0 || blockIdx.x != 0) return;
    const float* f = (const float*)mask;
    const int*   ip = (const int*)mask;
    bool f32ok = true, has1 = false;
    for (int i = 0; i < 1024; i++) {
        float v = f[i];
        if (!(v == 0.0f || v == 1.0f)) { f32ok = false; break; }
        if (v == 1.0f) has1 = true;
    }
    if (f32ok && has1) { g_mask_mode = 2; return; }
    bool i32ok = true;
    for (int i = 0; i < 1024; i++) {
        int v = ip[i];
        if (v != 0 && v != 1) { i32ok = false; break; }
    }
    g_mask_mode = i32ok ? 1 : 0;
}

// ---------------------------------------------------------------------------
// tf32 helpers
// ---------------------------------------------------------------------------
__device__ __forceinline__ unsigned f2tf(float x) {
    unsigned u;
    asm("cvt.rna.tf32.f32 %0, %1;" : "=r"(u) : "f"(x));
    return u;
}

__device__ __forceinline__ void mma8(float* d, const unsigned* a, const unsigned* b) {
    asm volatile(
        "mma.sync.aligned.m16n8k8.row.col.f32.tf32.tf32.f32 "
        "{%0,%1,%2,%3},{%4,%5,%6,%7},{%8,%9},{%0,%1,%2,%3};"
        : "+f"(d[0]), "+f"(d[1]), "+f"(d[2]), "+f"(d[3])
        : "r"(a[0]), "r"(a[1]), "r"(a[2]), "r"(a[3]), "r"(b[0]), "r"(b[1]));
}

// ---------------------------------------------------------------------------
// NT tf32 GEMM (projections / out-proj): C[m,n] = sum_k A[m,k]*W[n,k] (+bias)
// Block tile 128x64, BK=32, 8 warps, warp tile 32x32.
// ---------------------------------------------------------------------------
__global__ void __launch_bounds__(256)
gemm_nt_tf32(const float* __restrict__ A, const float* __restrict__ W,
             const float* __restrict__ bias, float* __restrict__ C)
{
    __shared__ unsigned As[128][36];
    __shared__ unsigned Bs[64][36];
    const int tid  = threadIdx.x;
    const int warp = tid >> 5, lane = tid & 31;
    const int g = lane >> 2, t = lane & 3;
    const int wm = (warp >> 1) << 5, wn = (warp & 1) << 5;
    const int m0 = blockIdx.y << 7, n0 = blockIdx.x << 6;

    const int ar = tid >> 1, ac = (tid & 1) << 4;
    const int br = tid >> 2, bc = (tid & 3) << 3;

    float acc[2][4][4] = {};

    for (int k0 = 0; k0 < D_; k0 += 32) {
        const float* Ap = A + (size_t)(m0 + ar) * D_ + k0 + ac;
        const float* Wp = W + (size_t)(n0 + br) * D_ + k0 + bc;
        float4 a0 = *(const float4*)(Ap + 0);
        float4 a1 = *(const float4*)(Ap + 4);
        float4 a2 = *(const float4*)(Ap + 8);
        float4 a3 = *(const float4*)(Ap + 12);
        float4 b0 = *(const float4*)(Wp + 0);
        float4 b1 = *(const float4*)(Wp + 4);
        __syncthreads();
        *(uint4*)&As[ar][ac + 0]  = make_uint4(f2tf(a0.x), f2tf(a0.y), f2tf(a0.z), f2tf(a0.w));
        *(uint4*)&As[ar][ac + 4]  = make_uint4(f2tf(a1.x), f2tf(a1.y), f2tf(a1.z), f2tf(a1.w));
        *(uint4*)&As[ar][ac + 8]  = make_uint4(f2tf(a2.x), f2tf(a2.y), f2tf(a2.z), f2tf(a2.w));
        *(uint4*)&As[ar][ac + 12] = make_uint4(f2tf(a3.x), f2tf(a3.y), f2tf(a3.z), f2tf(a3.w));
        *(uint4*)&Bs[br][bc + 0]  = make_uint4(f2tf(b0.x), f2tf(b0.y), f2tf(b0.z), f2tf(b0.w));
        *(uint4*)&Bs[br][bc + 4]  = make_uint4(f2tf(b1.x), f2tf(b1.y), f2tf(b1.z), f2tf(b1.w));
        __syncthreads();
        #pragma unroll
        for (int kk = 0; kk < 4; kk++) {
            const int k8 = kk << 3;
            unsigned af[2][4], bf[4][2];
            #pragma unroll
            for (int mt = 0; mt < 2; mt++) {
                const int r = wm + (mt << 4) + g;
                af[mt][0] = As[r][k8 + t];
                af[mt][1] = As[r + 8][k8 + t];
                af[mt][2] = As[r][k8 + t + 4];
                af[mt][3] = As[r + 8][k8 + t + 4];
            }
            #pragma unroll
            for (int nt = 0; nt < 4; nt++) {
                const int r = wn + (nt << 3) + g;
                bf[nt][0] = Bs[r][k8 + t];
                bf[nt][1] = Bs[r][k8 + t + 4];
            }
            #pragma unroll
            for (int mt = 0; mt < 2; mt++)
                #pragma unroll
                for (int nt = 0; nt < 4; nt++)
                    mma8(acc[mt][nt], af[mt], bf[nt]);
        }
    }

    #pragma unroll
    for (int mt = 0; mt < 2; mt++) {
        #pragma unroll
        for (int nt = 0; nt < 4; nt++) {
            const int row = m0 + wm + (mt << 4) + g;
            const int col = n0 + wn + (nt << 3) + (t << 1);
            float bv0 = bias ? bias[col] : 0.0f;
            float bv1 = bias ? bias[col + 1] : 0.0f;
            C[(size_t)row * D_ + col]           = acc[mt][nt][0] + bv0;
            C[(size_t)row * D_ + col + 1]       = acc[mt][nt][1] + bv1;
            C[(size_t)(row + 8) * D_ + col]     = acc[mt][nt][2] + bv0;
            C[(size_t)(row + 8) * D_ + col + 1] = acc[mt][nt][3] + bv1;
        }
    }
}

// ---------------------------------------------------------------------------
// FUSED: per (bh, 16-row q-strip) compute
//   content scores [16x1024]  (qh+u)  . kh^T
//   pos scores P   [17x1024]  (qh+vb) . ph^T      (row 17 via scalar dot)
//   then shift + mask + scale + row softmax -> write attn ONCE.
// shift(q,k): k<=q -> P[q, k+(S-1-q)] ; k==q+1 -> 0 ; k>q+1 -> P[q+1, k-q-2]
// Dynamic SMEM layout (words):
//   Ssc[16*1024] | Pp[17*1024] | KT[128*68] | PT[128*68] | Acon[16*64] | Apos[17*64]
// ---------------------------------------------------------------------------
#define SS_OFF 0
#define PP_OFF (16 * 1024)
#define KT_OFF (PP_OFF + 17 * 1024)
#define PT_OFF (KT_OFF + 128 * 68)
#define AC_OFF (PT_OFF + 128 * 68)
#define AP_OFF (AC_OFF + 16 * 64)
#define FUSED_SMEM_WORDS (AP_OFF + 17 * 64)
#define FUSED_SMEM_BYTES (FUSED_SMEM_WORDS * 4)

__global__ void __launch_bounds__(256)
fused_score_softmax(const float* __restrict__ u_bias,
                    const float* __restrict__ v_bias,
                    const void* __restrict__ mask,
                    float* __restrict__ attnout)
{
    extern __shared__ float sm[];
    float*    Ssc  = sm + SS_OFF;
    float*    Pp   = sm + PP_OFF;
    unsigned* KT   = (unsigned*)(sm + KT_OFF);
    unsigned* PT   = (unsigned*)(sm + PT_OFF);
    float*    Acon = sm + AC_OFF;
    float*    Apos = sm + AP_OFF;

    const int bh = blockIdx.y, b = bh >> 3, h = bh & 7;
    const int q0 = blockIdx.x << 4;
    const int tid  = threadIdx.x;
    const int warp = tid >> 5, lane = tid & 31;
    const int g = lane >> 2, t = lane & 3;

    // ---- load A rows: qh[q0 .. q0+16] (+u for content rows, +vb for pos rows)
    for (int idx = tid; idx < 17 * 64; idx += 256) {
        const int r = idx >> 6, d = idx & 63;
        const int qg = q0 + r;
        float qv = (qg < S_) ? g_qh[(size_t)((b << 10) + qg) * D_ + (h << 6) + d] : 0.0f;
        if (r < 16) Acon[idx] = qv + u_bias[(h << 6) + d];
        Apos[idx] = qv + v_bias[(h << 6) + d];
    }
    __syncthreads();

    // ---- A fragments in registers (M=16 tile), 8 k-steps
    unsigned afc[8][4], afp[8][4];
    #pragma unroll
    for (int kk = 0; kk < 8; kk++) {
        const int k8 = kk << 3;
        afc[kk][0] = f2tf(Acon[(g)     * 64 + k8 + t]);
        afc[kk][1] = f2tf(Acon[(g + 8) * 64 + k8 + t]);
        afc[kk][2] = f2tf(Acon[(g)     * 64 + k8 + t + 4]);
        afc[kk][3] = f2tf(Acon[(g + 8) * 64 + k8 + t + 4]);
        afp[kk][0] = f2tf(Apos[(g)     * 64 + k8 + t]);
        afp[kk][1] = f2tf(Apos[(g + 8) * 64 + k8 + t]);
        afp[kk][2] = f2tf(Apos[(g)     * 64 + k8 + t + 4]);
        afp[kk][3] = f2tf(Apos[(g + 8) * 64 + k8 + t + 4]);
    }

    // ---- loop over 8 column tiles of 128
    for (int ntile = 0; ntile < 8; ntile++) {
        const int n0 = ntile << 7;
        __syncthreads();   // previous readers of KT/PT done
        // stage kh/ph tiles [128 x 64] (tf32-converted), row pad 68
        for (int i = tid; i < 2048; i += 256) {
            const int r = i >> 4, c4 = (i & 15) << 2;
            const size_t gofs = (size_t)((b << 10) + n0 + r) * D_ + (h << 6) + c4;
            float4 kv = *(const float4*)&g_kh[gofs];
            float4 pv = *(const float4*)&g_ph[gofs];
            *(uint4*)&KT[r * 68 + c4] = make_uint4(f2tf(kv.x), f2tf(kv.y), f2tf(kv.z), f2tf(kv.w));
            *(uint4*)&PT[r * 68 + c4] = make_uint4(f2tf(pv.x), f2tf(pv.y), f2tf(pv.z), f2tf(pv.w));
        }
        __syncthreads();

        // MMA: warp covers 16 cols (2 n8 tiles) of this 128-col tile
        float accC[2][4] = {}, accP[2][4] = {};
        #pragma unroll
        for (int kk = 0; kk < 8; kk++) {
            const int k8 = kk << 3;
            #pragma unroll
            for (int nt = 0; nt < 2; nt++) {
                const int row = (warp << 4) + (nt << 3) + g;
                unsigned bk[2], bp[2];
                bk[0] = KT[row * 68 + k8 + t];
                bk[1] = KT[row * 68 + k8 + t + 4];
                bp[0] = PT[row * 68 + k8 + t];
                bp[1] = PT[row * 68 + k8 + t + 4];
                mma8(accC[nt], afc[kk], bk);
                mma8(accP[nt], afp[kk], bp);
            }
        }
        // write scores to SMEM
        #pragma unroll
        for (int nt = 0; nt < 2; nt++) {
            const int col = n0 + (warp << 4) + (nt << 3) + (t << 1);
            Ssc[(g)     * 1024 + col]     = accC[nt][0];
            Ssc[(g)     * 1024 + col + 1] = accC[nt][1];
            Ssc[(g + 8) * 1024 + col]     = accC[nt][2];
            Ssc[(g + 8) * 1024 + col + 1] = accC[nt][3];
            Pp[(g)      * 1024 + col]     = accP[nt][0];
            Pp[(g)      * 1024 + col + 1] = accP[nt][1];
            Pp[(g + 8)  * 1024 + col]     = accP[nt][2];
            Pp[(g + 8)  * 1024 + col + 1] = accP[nt][3];
        }
        // P row 16 (only needed for q = q0+15, k > q+1): scalar dot, 128 threads
        if (tid < 128) {
            float s = 0.0f;
            #pragma unroll 8
            for (int d = 0; d < 64; d++)
                s += Apos[16 * 64 + d] * __uint_as_float(PT[tid * 68 + d]);
            Pp[16 * 1024 + n0 + tid] = s;
        }
    }
    __syncthreads();

    // ---- epilogue: shift + mask + scale + softmax ; warp w -> rows 2w, 2w+1
    const float scale = 0.04419417382415922f;  // 1/sqrt(512)
    const int mm = g_mask_mode;
    #pragma unroll
    for (int rr = 0; rr < 2; rr++) {
        const int r = (warp << 1) + rr;
        const int q = q0 + r;
        const int off1 = (S_ - 1) - q;
        const size_t midx0 = ((size_t)b << 20) + ((size_t)q << 10);
        float vals[32];
        float mx = -1e30f;
        #pragma unroll
        for (int c = 0; c < 32; c++) {
            const int k = (c << 5) + lane;
            float p;
            if (k <= q)          p = Pp[r * 1024 + k + off1];
            else if (k == q + 1) p = 0.0f;
            else                 p = Pp[(r + 1) * 1024 + (k - q - 2)];
            float sc = (Ssc[r * 1024 + k] + p) * scale;
            bool msk;
            if (mm == 1)      msk = ((const int*)mask)[midx0 + k] != 0;
            else if (mm == 2) msk = ((const float*)mask)[midx0 + k] != 0.0f;
            else              msk = ((const unsigned char*)mask)[midx0 + k] != 0;
            vals[c] = msk ? -10000.0f : sc;
            mx = fmaxf(mx, vals[c]);
        }
        #pragma unroll
        for (int o = 16; o > 0; o >>= 1) mx = fmaxf(mx, __shfl_xor_sync(0xffffffffu, mx, o));
        float sum = 0.0f;
        #pragma unroll
        for (int c = 0; c < 32; c++) {
            vals[c] = __expf(vals[c] - mx);
            sum += vals[c];
        }
        #pragma unroll
        for (int o = 16; o > 0; o >>= 1) sum += __shfl_xor_sync(0xffffffffu, sum, o);
        const float inv = 1.0f / sum;
        float* orow = attnout + ((size_t)bh << 20) + ((size_t)q << 10);
        #pragma unroll
        for (int c = 0; c < 32; c++)
            orow[(c << 5) + lane] = vals[c] * inv;
    }
}

// ---------------------------------------------------------------------------
// Batched AV GEMM per (b,h): ctx[q, hd] = sum_k attn[q,k] * vh[k, hd]
// M=1024, N=64, K=1024. Block 128x64, BK=32, tf32 mma.
// ---------------------------------------------------------------------------
__global__ void __launch_bounds__(256)
av_tf32(const float* __restrict__ attn)
{
    __shared__ unsigned As[128][36];
    __shared__ unsigned Bs[32][72];
    const int bh = blockIdx.z, b = bh >> 3, h = bh & 7;
    const int tid  = threadIdx.x;
    const int warp = tid >> 5, lane = tid & 31;
    const int g = lane >> 2, t = lane & 3;
    const int wm = (warp >> 1) << 5, wn = (warp & 1) << 5;
    const int m0 = blockIdx.y << 7;

    const int ar = tid >> 1, ac = (tid & 1) << 4;
    const int vr = tid >> 3, vc = (tid & 7) << 3;

    float acc[2][4][4] = {};

    const float* Abase = attn + (size_t)bh * S_ * S_;

    for (int k0 = 0; k0 < S_; k0 += 32) {
        const float* Ap = Abase + (size_t)(m0 + ar) * S_ + k0 + ac;
        const float* Vp = g_vh + (size_t)((b << 10) + k0 + vr) * D_ + (h << 6) + vc;
        float4 a0 = *(const float4*)(Ap + 0);
        float4 a1 = *(const float4*)(Ap + 4);
        float4 a2 = *(const float4*)(Ap + 8);
        float4 a3 = *(const float4*)(Ap + 12);
        float4 v0 = *(const float4*)(Vp + 0);
        float4 v1 = *(const float4*)(Vp + 4);
        __syncthreads();
        *(uint4*)&As[ar][ac + 0]  = make_uint4(f2tf(a0.x), f2tf(a0.y), f2tf(a0.z), f2tf(a0.w));
        *(uint4*)&As[ar][ac + 4]  = make_uint4(f2tf(a1.x), f2tf(a1.y), f2tf(a1.z), f2tf(a1.w));
        *(uint4*)&As[ar][ac + 8]  = make_uint4(f2tf(a2.x), f2tf(a2.y), f2tf(a2.z), f2tf(a2.w));
        *(uint4*)&As[ar][ac + 12] = make_uint4(f2tf(a3.x), f2tf(a3.y), f2tf(a3.z), f2tf(a3.w));
        *(uint4*)&Bs[vr][vc + 0]  = make_uint4(f2tf(v0.x), f2tf(v0.y), f2tf(v0.z), f2tf(v0.w));
        *(uint4*)&Bs[vr][vc + 4]  = make_uint4(f2tf(v1.x), f2tf(v1.y), f2tf(v1.z), f2tf(v1.w));
        __syncthreads();
        #pragma unroll
        for (int kk = 0; kk < 4; kk++) {
            const int k8 = kk << 3;
            unsigned af[2][4], bf[4][2];
            #pragma unroll
            for (int mt = 0; mt < 2; mt++) {
                const int r = wm + (mt << 4) + g;
                af[mt][0] = As[r][k8 + t];
                af[mt][1] = As[r + 8][k8 + t];
                af[mt][2] = As[r][k8 + t + 4];
                af[mt][3] = As[r + 8][k8 + t + 4];
            }
            #pragma unroll
            for (int nt = 0; nt < 4; nt++) {
                const int c = wn + (nt << 3) + g;
                bf[nt][0] = Bs[k8 + t][c];
                bf[nt][1] = Bs[k8 + t + 4][c];
            }
            #pragma unroll
            for (int mt = 0; mt < 2; mt++)
                #pragma unroll
                for (int nt = 0; nt < 4; nt++)
                    mma8(acc[mt][nt], af[mt], bf[nt]);
        }
    }

    #pragma unroll
    for (int mt = 0; mt < 2; mt++)
        #pragma unroll
        for (int nt = 0; nt < 4; nt++) {
            const int q   = m0 + wm + (mt << 4) + g;
            const int col = (h << 6) + wn + (nt << 3) + (t << 1);
            g_ctx[(size_t)((b << 10) + q) * D_ + col]           = acc[mt][nt][0];
            g_ctx[(size_t)((b << 10) + q) * D_ + col + 1]       = acc[mt][nt][1];
            g_ctx[(size_t)((b << 10) + q + 8) * D_ + col]       = acc[mt][nt][2];
            g_ctx[(size_t)((b << 10) + q + 8) * D_ + col + 1]   = acc[mt][nt][3];
        }
}

// ---------------------------------------------------------------------------
// kernel_launch: graph-capturable pipeline, default stream, no allocations.
// Output layout: context [8,1024,512] then attn [8,8,1024,1024].
// ---------------------------------------------------------------------------
extern "C" void kernel_launch(void* const* d_in, const int* in_sizes, int n_in,
                              void* d_out, int out_size)
{
    const float* q    = (const float*)d_in[0];
    const float* k    = (const float*)d_in[1];
    const float* v    = (const float*)d_in[2];
    const float* pos  = (const float*)d_in[3];
    const void*  mask = d_in[4];
    const float* Wq   = (const float*)d_in[5];
    const float* bq   = (const float*)d_in[6];
    const float* Wk   = (const float*)d_in[7];
    const float* bk   = (const float*)d_in[8];
    const float* Wv   = (const float*)d_in[9];
    const float* bv   = (const float*)d_in[10];
    const float* Wpos = (const float*)d_in[11];
    const float* Wout = (const float*)d_in[12];
    const float* bout = (const float*)d_in[13];
    const float* u    = (const float*)d_in[14];
    const float* vb   = (const float*)d_in[15];

    float* out  = (float*)d_out;
    float* attn = out + (size_t)MT_ * D_;   // context first, then attn

    float *p_qh, *p_kh, *p_vh, *p_ph, *p_ctx;
    cudaGetSymbolAddress((void**)&p_qh,  g_qh);
    cudaGetSymbolAddress((void**)&p_kh,  g_kh);
    cudaGetSymbolAddress((void**)&p_vh,  g_vh);
    cudaGetSymbolAddress((void**)&p_ph,  g_ph);
    cudaGetSymbolAddress((void**)&p_ctx, g_ctx);

    static bool attr_set = false;
    if (!attr_set) {
        cudaFuncSetAttribute(fused_score_softmax,
                             cudaFuncAttributeMaxDynamicSharedMemorySize,
                             FUSED_SMEM_BYTES);
        attr_set = true;
    }

    detect_mask_kernel<<<1, 32>>>(mask);

    // Projections: x @ W^T + b  (tf32 tensor cores)
    dim3 gproj(D_ / 64, MT_ / 128);
    gemm_nt_tf32<<<gproj, 256>>>(q,   Wq,   bq,      p_qh);
    gemm_nt_tf32<<<gproj, 256>>>(k,   Wk,   bk,      p_kh);
    gemm_nt_tf32<<<gproj, 256>>>(v,   Wv,   bv,      p_vh);
    gemm_nt_tf32<<<gproj, 256>>>(pos, Wpos, nullptr, p_ph);

    // Fused: both score GEMMs + shift + mask + scale + softmax -> attn (once)
    dim3 gfused(S_ / 16, BH_);
    fused_score_softmax<<<gfused, 256, FUSED_SMEM_BYTES>>>(u, vb, mask, attn);

    // context heads = attn @ vh  (tf32)
    dim3 gav(1, S_ / 128, BH_);
    av_tf32<<<gav, 256>>>(attn);

    // Output projection: ctx @ Wout^T + bout -> d_out
    gemm_nt_tf32<<<gproj, 256>>>(p_ctx, Wout, bout, out);
}